// round 3
// baseline (speedup 1.0000x reference)
#include <cuda_runtime.h>
#include <cstdint>

#define NB 512
#define ND 512
#define NC 200000

static constexpr float cCOS_M  =  0.87758256189037271f;
static constexpr float cSIN_M  =  0.47942553860420301f;
static constexpr float cTHRESH = -0.87758256189037271f;
static constexpr float cMM     =  0.23971276930210150f;
static constexpr float cS      =  64.0f;
static constexpr float cEPS    =  1e-12f;

// Scratch (device globals; sanctioned scratch mechanism)
__device__ __align__(1024) float g_wtf[NC * ND];    // normalized weight, tf32-rounded
__device__ __align__(1024) float g_fn_tf[NB * ND];  // normalized feats, tf32-rounded
__device__ float g_fn[NB * ND];                     // normalized feats fp32 (exact target path)
__device__ float g_invw[NC];
__device__ float g_tl[NB];
__device__ float g_cosm[NB];
__device__ float g_final[NB];
__device__ float g_tnew;

// ---------------------------------------------------------------------------
// helpers
// ---------------------------------------------------------------------------
__device__ __forceinline__ uint32_t smem_u32(const void* p) {
    uint32_t a;
    asm("{ .reg .u64 t; cvta.to.shared.u64 t, %1; cvt.u32.u64 %0, t; }" : "=r"(a) : "l"(p));
    return a;
}
__device__ __forceinline__ float f2tf(float x) {
    uint32_t r;
    asm("cvt.rna.tf32.f32 %0, %1;" : "=r"(r) : "f"(x));
    return __uint_as_float(r);
}
#define CP_ASYNC16(dst, src) \
    asm volatile("cp.async.cg.shared.global [%0], [%1], 16;" :: "r"(dst), "l"(src) : "memory")
#define CP_COMMIT() asm volatile("cp.async.commit_group;" ::: "memory")
#define CP_WAIT2()  asm volatile("cp.async.wait_group 2;" ::: "memory")
#define CP_WAIT0()  asm volatile("cp.async.wait_group 0;" ::: "memory")

__device__ __forceinline__ void mma_tf32(float (&c)[4], const uint32_t (&a)[4],
                                         const uint32_t (&b)[2]) {
    asm volatile(
        "mma.sync.aligned.m16n8k8.row.col.f32.tf32.tf32.f32 "
        "{%0,%1,%2,%3}, {%4,%5,%6,%7}, {%8,%9}, {%0,%1,%2,%3};\n"
        : "+f"(c[0]), "+f"(c[1]), "+f"(c[2]), "+f"(c[3])
        : "r"(a[0]), "r"(a[1]), "r"(a[2]), "r"(a[3]), "r"(b[0]), "r"(b[1]));
}

// ---------------------------------------------------------------------------
// Kernel 1: normalize feats; fp32 copy + tf32-rounded copy
// ---------------------------------------------------------------------------
__global__ void k_norm_feats(const float* __restrict__ feats) {
    int b = blockIdx.x;
    int tid = threadIdx.x;
    const float* x = feats + (size_t)b * ND;
    float s = 0.f;
    for (int i = tid; i < ND; i += 128) { float v = x[i]; s += v * v; }
    for (int o = 16; o; o >>= 1) s += __shfl_xor_sync(0xffffffffu, s, o);
    __shared__ float red[4];
    __shared__ float sinv;
    if ((tid & 31) == 0) red[tid >> 5] = s;
    __syncthreads();
    if (tid == 0) sinv = 1.0f / fmaxf(sqrtf(red[0] + red[1] + red[2] + red[3]), cEPS);
    __syncthreads();
    float inv = sinv;
    for (int i = tid; i < ND; i += 128) {
        float v = x[i] * inv;
        g_fn[(size_t)b * ND + i] = v;
        g_fn_tf[(size_t)b * ND + i] = f2tf(v);
    }
}

// ---------------------------------------------------------------------------
// Kernel 2: weight prep — inv norms + normalized tf32-rounded copy
// ---------------------------------------------------------------------------
__global__ __launch_bounds__(256) void k_prep_w(const float* __restrict__ w) {
    int row = blockIdx.x * 8 + (threadIdx.x >> 5);
    if (row >= NC) return;
    int lane = threadIdx.x & 31;
    const float4* p = reinterpret_cast<const float4*>(w + (size_t)row * ND);
    float4 v[4];
    float s = 0.f;
#pragma unroll
    for (int i = 0; i < 4; i++) {
        v[i] = p[lane + 32 * i];
        s += v[i].x * v[i].x + v[i].y * v[i].y + v[i].z * v[i].z + v[i].w * v[i].w;
    }
    for (int o = 16; o; o >>= 1) s += __shfl_xor_sync(0xffffffffu, s, o);
    float inv = 1.0f / fmaxf(sqrtf(s), cEPS);
    if (lane == 0) g_invw[row] = inv;
    float4* q = reinterpret_cast<float4*>(g_wtf + (size_t)row * ND);
#pragma unroll
    for (int i = 0; i < 4; i++) {
        float4 o4;
        o4.x = f2tf(v[i].x * inv);
        o4.y = f2tf(v[i].y * inv);
        o4.z = f2tf(v[i].z * inv);
        o4.w = f2tf(v[i].w * inv);
        q[lane + 32 * i] = o4;
    }
}

// ---------------------------------------------------------------------------
// Kernel 3: exact fp32 target logits
// ---------------------------------------------------------------------------
__global__ void k_target(const float* __restrict__ w, const int* __restrict__ labels) {
    int b = blockIdx.x;
    int tid = threadIdx.x;
    int c = labels[b];
    const float* wr = w + (size_t)c * ND;
    const float* f = g_fn + (size_t)b * ND;
    float s = 0.f;
    for (int i = tid; i < ND; i += 128) s += f[i] * wr[i];
    for (int o = 16; o; o >>= 1) s += __shfl_xor_sync(0xffffffffu, s, o);
    __shared__ float red[4];
    if ((tid & 31) == 0) red[tid >> 5] = s;
    __syncthreads();
    if (tid == 0) {
        float tot = red[0] + red[1] + red[2] + red[3];
        g_tl[b] = fminf(fmaxf(tot * g_invw[c], -1.0f), 1.0f);
    }
}

// ---------------------------------------------------------------------------
// Kernel 4: t_new, cos_theta_m, final
// ---------------------------------------------------------------------------
__global__ void k_scalars(const float* __restrict__ t) {
    int b = threadIdx.x;
    float tl = g_tl[b];
    float s = tl;
    for (int o = 16; o; o >>= 1) s += __shfl_xor_sync(0xffffffffu, s, o);
    __shared__ float red[16];
    if ((b & 31) == 0) red[b >> 5] = s;
    __syncthreads();
    if (b == 0) {
        float tot = 0.f;
#pragma unroll
        for (int i = 0; i < 16; i++) tot += red[i];
        g_tnew = (tot / (float)NB) * 0.01f + 0.99f * t[0];
    }
    float st = sqrtf(fmaxf(1.0f - tl * tl, 0.0f));
    float cm = tl * cCOS_M - st * cSIN_M;
    g_cosm[b] = cm;
    g_final[b] = (tl > cTHRESH) ? cm : (tl - cMM);
}

// ---------------------------------------------------------------------------
// Kernel 5: tf32 mma.sync GEMM, cp.async 4-stage pipeline, fused epilogue
// CTA tile 128(m) x 128(n) x BK=16, 256 threads, 2 CTAs/SM
// ---------------------------------------------------------------------------
#define SPAD 20
#define STAGES 4
#define BK 16
#define KT (ND / BK)  // 32

__global__ __launch_bounds__(256, 2) void k_gemm(const int* __restrict__ labels,
                                                 float* __restrict__ out) {
    extern __shared__ __align__(128) float smem[];
    float (*As)[128][SPAD] = reinterpret_cast<float (*)[128][SPAD]>(smem);
    float (*Bs)[128][SPAD] = reinterpret_cast<float (*)[128][SPAD]>(smem + STAGES * 128 * SPAD);

    const int tid = threadIdx.x;
    const int warp = tid >> 5;
    const int lane = tid & 31;
    const int g = lane >> 2;
    const int tg = lane & 3;
    const int wm = (warp >> 2) * 64;   // 2 warps in m
    const int wn = (warp & 3) * 32;    // 4 warps in n

    const int bm0 = blockIdx.x * 128;  // m tile (fast dim -> weight L2 reuse)
    const int c0 = blockIdx.y * 128;   // class tile

    // cp.async staging: thread -> row tid>>1, two 16B chunks at cols (tid&1)*8 + {0,4}
    const int ra = tid >> 1;
    const int aoff = (tid & 1) * 8;
    const int rb = min(c0 + ra, NC - 1);  // clamp last tile rows
    const float* srcA = g_fn_tf + (size_t)(bm0 + ra) * ND + aoff;
    const float* srcB = g_wtf + (size_t)rb * ND + aoff;

    float acc[4][4][4];
#pragma unroll
    for (int mi = 0; mi < 4; mi++)
#pragma unroll
        for (int ni = 0; ni < 4; ni++)
#pragma unroll
            for (int r = 0; r < 4; r++) acc[mi][ni][r] = 0.f;

    // prologue: issue stages 0..2
#pragma unroll
    for (int s = 0; s < STAGES - 1; s++) {
        uint32_t da = smem_u32(&As[s][ra][aoff]);
        uint32_t db = smem_u32(&Bs[s][ra][aoff]);
        const float* sa = srcA + s * BK;
        const float* sb = srcB + s * BK;
        CP_ASYNC16(da, sa);
        CP_ASYNC16(da + 16, sa + 4);
        CP_ASYNC16(db, sb);
        CP_ASYNC16(db + 16, sb + 4);
        CP_COMMIT();
    }

    for (int kt = 0; kt < KT; kt++) {
        CP_WAIT2();
        __syncthreads();  // stage kt visible to all; all warps done with stage kt-1

        // issue stage kt+3 into buffer (kt+3)&3 (overwrites stage kt-1's buffer)
        if (kt + STAGES - 1 < KT) {
            int b = (kt + STAGES - 1) & (STAGES - 1);
            uint32_t da = smem_u32(&As[b][ra][aoff]);
            uint32_t db = smem_u32(&Bs[b][ra][aoff]);
            const float* sa = srcA + (kt + STAGES - 1) * BK;
            const float* sb = srcB + (kt + STAGES - 1) * BK;
            CP_ASYNC16(da, sa);
            CP_ASYNC16(da + 16, sa + 4);
            CP_ASYNC16(db, sb);
            CP_ASYNC16(db + 16, sb + 4);
        }
        CP_COMMIT();  // empty group at tail keeps wait_group accounting uniform

        const float (*Asb)[SPAD] = As[kt & (STAGES - 1)];
        const float (*Bsb)[SPAD] = Bs[kt & (STAGES - 1)];
#pragma unroll
        for (int ks = 0; ks < 2; ks++) {
            const int k0 = ks * 8;
            uint32_t af[4][4];
            uint32_t bf[4][2];
#pragma unroll
            for (int mi = 0; mi < 4; mi++) {
                const float* ap = &Asb[wm + mi * 16 + g][k0 + tg];
                af[mi][0] = __float_as_uint(ap[0]);
                af[mi][1] = __float_as_uint(ap[8 * SPAD]);
                af[mi][2] = __float_as_uint(ap[4]);
                af[mi][3] = __float_as_uint(ap[8 * SPAD + 4]);
            }
#pragma unroll
            for (int ni = 0; ni < 4; ni++) {
                const float* bp = &Bsb[wn + ni * 8 + g][k0 + tg];
                bf[ni][0] = __float_as_uint(bp[0]);
                bf[ni][1] = __float_as_uint(bp[4]);
            }
#pragma unroll
            for (int mi = 0; mi < 4; mi++)
#pragma unroll
                for (int ni = 0; ni < 4; ni++) mma_tf32(acc[mi][ni], af[mi], bf[ni]);
        }
    }
    CP_WAIT0();

    // ---- fused CurricularFace epilogue (weight pre-normalized -> acc is cos) ----
    const float tnew = g_tnew;
    int ccol[4];
#pragma unroll
    for (int ni = 0; ni < 4; ni++) ccol[ni] = c0 + wn + ni * 8 + 2 * tg;

#pragma unroll
    for (int mi = 0; mi < 4; mi++) {
#pragma unroll
        for (int h = 0; h < 2; h++) {
            int m = bm0 + wm + mi * 16 + g + h * 8;
            int lab = labels[m];
            float cm = g_cosm[m];
            float fi = g_final[m];
            float* orow = out + (size_t)m * NC;
#pragma unroll
            for (int ni = 0; ni < 4; ni++) {
                int c = ccol[ni];
                if (c + 1 < NC) {  // NC even: pair fully in-bounds or fully out
                    float x0 = fminf(fmaxf(acc[mi][ni][h * 2 + 0], -1.0f), 1.0f);
                    float x1 = fminf(fmaxf(acc[mi][ni][h * 2 + 1], -1.0f), 1.0f);
                    float v0 = (x0 > cm) ? x0 * (tnew + x0) : x0;
                    float v1 = (x1 > cm) ? x1 * (tnew + x1) : x1;
                    if (lab == c) v0 = fi;
                    if (lab == c + 1) v1 = fi;
                    float2 o;
                    o.x = v0 * cS;
                    o.y = v1 * cS;
                    *reinterpret_cast<float2*>(orow + c) = o;
                }
            }
        }
    }
}

// ---------------------------------------------------------------------------
extern "C" void kernel_launch(void* const* d_in, const int* in_sizes, int n_in,
                              void* d_out, int out_size) {
    const float* feats = (const float*)d_in[0];
    const int* labels = (const int*)d_in[1];
    const float* weight = (const float*)d_in[2];
    const float* t = (const float*)d_in[3];
    float* out = (float*)d_out;

    const int smem_bytes = STAGES * 128 * SPAD * 2 * (int)sizeof(float);  // 81920
    cudaFuncSetAttribute(k_gemm, cudaFuncAttributeMaxDynamicSharedMemorySize, smem_bytes);

    k_norm_feats<<<NB, 128>>>(feats);
    k_prep_w<<<(NC + 7) / 8, 256>>>(weight);
    k_target<<<NB, 128>>>(weight, labels);
    k_scalars<<<1, NB>>>(t);

    dim3 grid(4, (NC + 127) / 128);  // m-tile fast -> 4 CTAs share each weight tile in L2
    k_gemm<<<grid, 256, smem_bytes>>>(labels, out);
}

// round 4
// speedup vs baseline: 1.9648x; 1.9648x over previous
#include <cuda_runtime.h>
#include <cuda_fp16.h>
#include <cstdint>

#define NB 512
#define ND 512
#define NC 200000

static constexpr float cCOS_M  =  0.87758256189037271f;
static constexpr float cSIN_M  =  0.47942553860420301f;
static constexpr float cTHRESH = -0.87758256189037271f;
static constexpr float cMM     =  0.23971276930210150f;
static constexpr float cS      =  64.0f;
static constexpr float cEPS    =  1e-12f;

// Scratch (device globals; sanctioned scratch mechanism)
__device__ __align__(1024) __half g_wh[NC * ND];   // normalized weight, fp16
__device__ __align__(1024) __half g_fh[NB * ND];   // normalized feats, fp16
__device__ float g_fn[NB * ND];                    // normalized feats fp32 (exact target path)
__device__ float g_invw[NC];
__device__ float g_tl[NB];
__device__ float g_cosm[NB];
__device__ float g_final[NB];
__device__ float g_tnew;

// ---------------------------------------------------------------------------
// helpers
// ---------------------------------------------------------------------------
__device__ __forceinline__ uint32_t smem_u32(const void* p) {
    uint32_t a;
    asm("{ .reg .u64 t; cvta.to.shared.u64 t, %1; cvt.u32.u64 %0, t; }" : "=r"(a) : "l"(p));
    return a;
}
#define CP_ASYNC16(dst, src) \
    asm volatile("cp.async.cg.shared.global [%0], [%1], 16;" :: "r"(dst), "l"(src) : "memory")
#define CP_COMMIT() asm volatile("cp.async.commit_group;" ::: "memory")
#define CP_WAIT2()  asm volatile("cp.async.wait_group 2;" ::: "memory")
#define CP_WAIT0()  asm volatile("cp.async.wait_group 0;" ::: "memory")

__device__ __forceinline__ void mma_f16(float (&c)[4], const uint32_t (&a)[4],
                                        const uint32_t (&b)[2]) {
    asm volatile(
        "mma.sync.aligned.m16n8k16.row.col.f32.f16.f16.f32 "
        "{%0,%1,%2,%3}, {%4,%5,%6,%7}, {%8,%9}, {%0,%1,%2,%3};\n"
        : "+f"(c[0]), "+f"(c[1]), "+f"(c[2]), "+f"(c[3])
        : "r"(a[0]), "r"(a[1]), "r"(a[2]), "r"(a[3]), "r"(b[0]), "r"(b[1]));
}
#define LDMX4(r0, r1, r2, r3, addr)                                           \
    asm volatile("ldmatrix.sync.aligned.m8n8.x4.shared.b16 {%0,%1,%2,%3}, [%4];" \
                 : "=r"(r0), "=r"(r1), "=r"(r2), "=r"(r3) : "r"(addr))
#define LDMX2(r0, r1, addr)                                                   \
    asm volatile("ldmatrix.sync.aligned.m8n8.x2.shared.b16 {%0,%1}, [%2];"    \
                 : "=r"(r0), "=r"(r1) : "r"(addr))

// ---------------------------------------------------------------------------
// Kernel 1: normalize feats; fp32 copy + fp16 copy
// ---------------------------------------------------------------------------
__global__ void k_norm_feats(const float* __restrict__ feats) {
    int b = blockIdx.x;
    int tid = threadIdx.x;
    const float* x = feats + (size_t)b * ND;
    float s = 0.f;
    for (int i = tid; i < ND; i += 128) { float v = x[i]; s += v * v; }
    for (int o = 16; o; o >>= 1) s += __shfl_xor_sync(0xffffffffu, s, o);
    __shared__ float red[4];
    __shared__ float sinv;
    if ((tid & 31) == 0) red[tid >> 5] = s;
    __syncthreads();
    if (tid == 0) sinv = 1.0f / fmaxf(sqrtf(red[0] + red[1] + red[2] + red[3]), cEPS);
    __syncthreads();
    float inv = sinv;
    for (int i = tid; i < ND; i += 128) {
        float v = x[i] * inv;
        g_fn[(size_t)b * ND + i] = v;
        g_fh[(size_t)b * ND + i] = __float2half_rn(v);
    }
}

// ---------------------------------------------------------------------------
// Kernel 2: weight prep — inv norms + normalized fp16 copy
// ---------------------------------------------------------------------------
__global__ __launch_bounds__(256) void k_prep_w(const float* __restrict__ w) {
    int row = blockIdx.x * 8 + (threadIdx.x >> 5);
    if (row >= NC) return;
    int lane = threadIdx.x & 31;
    const float4* p = reinterpret_cast<const float4*>(w + (size_t)row * ND);
    float4 v[4];
    float s = 0.f;
#pragma unroll
    for (int i = 0; i < 4; i++) {
        v[i] = p[lane + 32 * i];
        s += v[i].x * v[i].x + v[i].y * v[i].y + v[i].z * v[i].z + v[i].w * v[i].w;
    }
    for (int o = 16; o; o >>= 1) s += __shfl_xor_sync(0xffffffffu, s, o);
    float inv = 1.0f / fmaxf(sqrtf(s), cEPS);
    if (lane == 0) g_invw[row] = inv;
    uint2* q = reinterpret_cast<uint2*>(g_wh + (size_t)row * ND);
#pragma unroll
    for (int i = 0; i < 4; i++) {
        __half2 h0 = __floats2half2_rn(v[i].x * inv, v[i].y * inv);
        __half2 h1 = __floats2half2_rn(v[i].z * inv, v[i].w * inv);
        uint2 u;
        u.x = *reinterpret_cast<uint32_t*>(&h0);
        u.y = *reinterpret_cast<uint32_t*>(&h1);
        q[lane + 32 * i] = u;
    }
}

// ---------------------------------------------------------------------------
// Kernel 3: exact fp32 target logits
// ---------------------------------------------------------------------------
__global__ void k_target(const float* __restrict__ w, const int* __restrict__ labels) {
    int b = blockIdx.x;
    int tid = threadIdx.x;
    int c = labels[b];
    const float* wr = w + (size_t)c * ND;
    const float* f = g_fn + (size_t)b * ND;
    float s = 0.f;
    for (int i = tid; i < ND; i += 128) s += f[i] * wr[i];
    for (int o = 16; o; o >>= 1) s += __shfl_xor_sync(0xffffffffu, s, o);
    __shared__ float red[4];
    if ((tid & 31) == 0) red[tid >> 5] = s;
    __syncthreads();
    if (tid == 0) {
        float tot = red[0] + red[1] + red[2] + red[3];
        g_tl[b] = fminf(fmaxf(tot * g_invw[c], -1.0f), 1.0f);
    }
}

// ---------------------------------------------------------------------------
// Kernel 4: t_new, cos_theta_m, final
// ---------------------------------------------------------------------------
__global__ void k_scalars(const float* __restrict__ t) {
    int b = threadIdx.x;
    float tl = g_tl[b];
    float s = tl;
    for (int o = 16; o; o >>= 1) s += __shfl_xor_sync(0xffffffffu, s, o);
    __shared__ float red[16];
    if ((b & 31) == 0) red[b >> 5] = s;
    __syncthreads();
    if (b == 0) {
        float tot = 0.f;
#pragma unroll
        for (int i = 0; i < 16; i++) tot += red[i];
        g_tnew = (tot / (float)NB) * 0.01f + 0.99f * t[0];
    }
    float st = sqrtf(fmaxf(1.0f - tl * tl, 0.0f));
    float cm = tl * cCOS_M - st * cSIN_M;
    g_cosm[b] = cm;
    g_final[b] = (tl > cTHRESH) ? cm : (tl - cMM);
}

// ---------------------------------------------------------------------------
// Kernel 5: fp16 mma.sync m16n8k16 GEMM, cp.async 4-stage pipeline, fused epilogue
// CTA tile 128(m) x 128(n) x BK=16, 256 threads, 2 CTAs/SM
// ---------------------------------------------------------------------------
#define SPAD_H 24      // halfs per smem row (48B) -> conflict-free ldmatrix
#define STAGES 4
#define BK 16
#define KT (ND / BK)   // 32

__global__ __launch_bounds__(256, 2) void k_gemm(const int* __restrict__ labels,
                                                 float* __restrict__ out) {
    extern __shared__ __align__(128) __half smem[];
    __half (*As)[128][SPAD_H] = reinterpret_cast<__half (*)[128][SPAD_H]>(smem);
    __half (*Bs)[128][SPAD_H] =
        reinterpret_cast<__half (*)[128][SPAD_H]>(smem + STAGES * 128 * SPAD_H);

    const int tid = threadIdx.x;
    const int warp = tid >> 5;
    const int lane = tid & 31;
    const int g = lane >> 2;
    const int tg = lane & 3;
    const int wm = (warp >> 2) * 64;   // 2 warps in m
    const int wn = (warp & 3) * 32;    // 4 warps in n

    const int bm0 = blockIdx.x * 128;  // m tile (fast dim -> weight L2 reuse)
    const int c0 = blockIdx.y * 128;   // class tile

    // cp.async staging: 128 rows x 32B per stage per operand; 256 threads x 16B
    const int ra = tid >> 1;
    const int aoff = (tid & 1) * 8;    // halfs
    const int rb = min(c0 + ra, NC - 1);
    const __half* srcA = g_fh + (size_t)(bm0 + ra) * ND + aoff;
    const __half* srcB = g_wh + (size_t)rb * ND + aoff;

    // ldmatrix addresses (per-lane, stage-invariant offsets)
    const int a_row = wm + (lane & 15);
    const int a_col = (lane >> 4) * 8;
    const int b_row = wn + (lane & 7);
    const int b_col = ((lane >> 3) & 1) * 8;

    float acc[4][4][4];
#pragma unroll
    for (int mi = 0; mi < 4; mi++)
#pragma unroll
        for (int ni = 0; ni < 4; ni++)
#pragma unroll
            for (int r = 0; r < 4; r++) acc[mi][ni][r] = 0.f;

    // prologue: stages 0..2
#pragma unroll
    for (int s = 0; s < STAGES - 1; s++) {
        CP_ASYNC16(smem_u32(&As[s][ra][aoff]), srcA + s * BK);
        CP_ASYNC16(smem_u32(&Bs[s][ra][aoff]), srcB + s * BK);
        CP_COMMIT();
    }

    for (int kt = 0; kt < KT; kt++) {
        CP_WAIT2();
        __syncthreads();

        if (kt + STAGES - 1 < KT) {
            int b = (kt + STAGES - 1) & (STAGES - 1);
            CP_ASYNC16(smem_u32(&As[b][ra][aoff]), srcA + (kt + STAGES - 1) * BK);
            CP_ASYNC16(smem_u32(&Bs[b][ra][aoff]), srcB + (kt + STAGES - 1) * BK);
        }
        CP_COMMIT();

        const __half (*Asb)[SPAD_H] = As[kt & (STAGES - 1)];
        const __half (*Bsb)[SPAD_H] = Bs[kt & (STAGES - 1)];

        uint32_t af[4][4];
        uint32_t bf[4][2];
#pragma unroll
        for (int mi = 0; mi < 4; mi++) {
            uint32_t addr = smem_u32(&Asb[a_row + mi * 16][a_col]);
            LDMX4(af[mi][0], af[mi][1], af[mi][2], af[mi][3], addr);
        }
#pragma unroll
        for (int ni = 0; ni < 4; ni++) {
            uint32_t addr = smem_u32(&Bsb[b_row + ni * 8][b_col]);
            LDMX2(bf[ni][0], bf[ni][1], addr);
        }
#pragma unroll
        for (int mi = 0; mi < 4; mi++)
#pragma unroll
            for (int ni = 0; ni < 4; ni++) mma_f16(acc[mi][ni], af[mi], bf[ni]);
    }
    CP_WAIT0();

    // ---- fused CurricularFace epilogue (weight pre-normalized -> acc is cos) ----
    const float tnew = g_tnew;
    int ccol[4];
#pragma unroll
    for (int ni = 0; ni < 4; ni++) ccol[ni] = c0 + wn + ni * 8 + 2 * tg;

#pragma unroll
    for (int mi = 0; mi < 4; mi++) {
#pragma unroll
        for (int h = 0; h < 2; h++) {
            int m = bm0 + wm + mi * 16 + g + h * 8;
            int lab = labels[m];
            float cm = g_cosm[m];
            float fi = g_final[m];
            float* orow = out + (size_t)m * NC;
#pragma unroll
            for (int ni = 0; ni < 4; ni++) {
                int c = ccol[ni];
                if (c + 1 < NC) {  // NC even: pair fully in-bounds or fully out
                    float x0 = fminf(fmaxf(acc[mi][ni][h * 2 + 0], -1.0f), 1.0f);
                    float x1 = fminf(fmaxf(acc[mi][ni][h * 2 + 1], -1.0f), 1.0f);
                    float v0 = (x0 > cm) ? x0 * (tnew + x0) : x0;
                    float v1 = (x1 > cm) ? x1 * (tnew + x1) : x1;
                    if (lab == c) v0 = fi;
                    if (lab == c + 1) v1 = fi;
                    float2 o;
                    o.x = v0 * cS;
                    o.y = v1 * cS;
                    *reinterpret_cast<float2*>(orow + c) = o;
                }
            }
        }
    }
}

// ---------------------------------------------------------------------------
extern "C" void kernel_launch(void* const* d_in, const int* in_sizes, int n_in,
                              void* d_out, int out_size) {
    const float* feats = (const float*)d_in[0];
    const int* labels = (const int*)d_in[1];
    const float* weight = (const float*)d_in[2];
    const float* t = (const float*)d_in[3];
    float* out = (float*)d_out;

    const int smem_bytes = STAGES * 128 * SPAD_H * 2 * (int)sizeof(__half);  // 49152
    cudaFuncSetAttribute(k_gemm, cudaFuncAttributeMaxDynamicSharedMemorySize, smem_bytes);

    k_norm_feats<<<NB, 128>>>(feats);
    k_prep_w<<<(NC + 7) / 8, 256>>>(weight);
    k_target<<<NB, 128>>>(weight, labels);
    k_scalars<<<1, NB>>>(t);

    dim3 grid(4, (NC + 127) / 128);  // m-tile fast -> 4 CTAs share each weight tile in L2
    k_gemm<<<grid, 256, smem_bytes>>>(labels, out);
}